// round 13
// baseline (speedup 1.0000x reference)
#include <cuda_runtime.h>

// GlobalFilter: y = irfft2(rfft2(x, ortho) * W, ortho)
// x: [128,14,14,768] f32, W: [14,8,768,2] f32.
// R13 = R12 math (double-folded DFTs, pair-slot smem) with register-peak
//       reduction (pass A per-kw pair emit w/ batched loads; pass B fused
//       inverse-fold2, EZ/OZS never materialized) + 5 CTAs/SM.

#define CC  768
#define CB  32
#define NTH 256

typedef unsigned long long ull;

__device__ __forceinline__ ull pk(float lo, float hi) {
    ull r; asm("mov.b64 %0, {%1,%2};" : "=l"(r) : "f"(lo), "f"(hi)); return r;
}
__device__ __forceinline__ void upk(ull v, float& lo, float& hi) {
    asm("mov.b64 {%0,%1}, %2;" : "=f"(lo), "=f"(hi) : "l"(v));
}
__device__ __forceinline__ ull swp(ull v) {
    float lo, hi; upk(v, lo, hi); return pk(hi, lo);
}
__device__ __forceinline__ ull f2fma(ull a, ull b, ull c) {
    ull d; asm("fma.rn.f32x2 %0, %1, %2, %3;" : "=l"(d) : "l"(a), "l"(b), "l"(c)); return d;
}
__device__ __forceinline__ ull f2add(ull a, ull b) {
    ull d; asm("add.rn.f32x2 %0, %1, %2;" : "=l"(d) : "l"(a), "l"(b)); return d;
}
__device__ __forceinline__ ull f2sub(ull a, ull b) {
    ull d; asm("sub.rn.f32x2 %0, %1, %2;" : "=l"(d) : "l"(a), "l"(b)); return d;
}
__host__ __device__ constexpr ull pkc(float lo, float hi) {
    return (ull)__builtin_bit_cast(unsigned int, lo)
         | ((ull)__builtin_bit_cast(unsigned int, hi) << 32);
}
#define CP(v) pkc(v, v)
__device__ __forceinline__ ull cmulw(ull X, float2 w) {
    float xr, xi; upk(X, xr, xi);
    return pk(fmaf(-xi, w.y, xr * w.x), fmaf(xi, w.x, xr * w.y));
}
__device__ __forceinline__ void stcs(float* p, float v) {
    asm volatile("st.global.cs.f32 [%0], %1;" :: "l"(p), "f"(v) : "memory");
}

#define DEF_TWIDDLES \
    constexpr float COS14[14] = { \
         1.0f,                 0.9009688679024191f,  0.6234898018587336f, \
         0.22252093395631445f,-0.22252093395631445f,-0.6234898018587336f, \
        -0.9009688679024191f, -1.0f,                -0.9009688679024191f, \
        -0.6234898018587336f, -0.22252093395631445f, 0.22252093395631445f, \
         0.6234898018587336f,  0.9009688679024191f }; \
    constexpr float SIN14[14] = { \
         0.0f,                 0.43388373911755823f, 0.7818314824680298f, \
         0.9749279121818236f,  0.9749279121818236f,  0.7818314824680298f, \
         0.43388373911755823f, 0.0f,                -0.43388373911755823f, \
        -0.7818314824680298f, -0.9749279121818236f, -0.9749279121818236f, \
        -0.7818314824680298f, -0.43388373911755823f }

// Forward H-DFT step for a compile-time kh: C/T from double-folded inputs.
template<int KH>
__device__ __forceinline__ void fwd_step(const ull EP[4], const ull EM[4],
                                         const ull OSM[4], const ull OSP[4],
                                         ull fbp, ull fbm, ull& C, ull& T)
{
    DEF_TWIDDLES;
    C = (KH & 1) ? fbm : fbp;
    T = 0ull;
    #pragma unroll
    for (int j = 1; j <= 3; ++j) {
        const int m = (KH * j) % 14;
        C = f2fma((KH & 1) ? EM[j] : EP[j], CP(COS14[m]), C);
        if ((KH % 7) != 0)
            T = f2fma((KH & 1) ? OSP[j] : OSM[j],
                      pkc(SIN14[m], -SIN14[m]), T);
    }
}

// Double-folded c2r of one row of Y1 over W + streaming store (scale folded).
__device__ __forceinline__ void c2r_row(float* __restrict__ yb,
                                        int h, const ull yv[8])
{
    DEF_TWIDDLES;
    constexpr float INV98  = 1.0f / 98.0f;
    constexpr float INV196 = 1.0f / 196.0f;
    float yr0, yi0, yr7, yi7;
    upk(yv[0], yr0, yi0); upk(yv[7], yr7, yi7);
    const float b0 = yr0 * INV196, b7 = yr7 * INV196;
    const float bse_e = b0 + b7, bse_o = b0 - b7;
    ull yP[4], yM[4];
    #pragma unroll
    for (int kw = 1; kw <= 3; ++kw) {
        yP[kw] = f2fma(yv[7 - kw], pkc( 1.f, -1.f), yv[kw]);
        yM[kw] = f2fma(yv[7 - kw], pkc(-1.f,  1.f), yv[kw]);
    }
    #pragma unroll
    for (int w = 0; w < 8; ++w) {
        ull acc = pk((w & 1) ? bse_o : bse_e, 0.f);  // (C, S)
        #pragma unroll
        for (int kw = 1; kw <= 3; ++kw) {
            const int m = (kw * w) % 14;
            acc = f2fma((w & 1) ? yM[kw] : yP[kw],
                        pkc(COS14[m] * INV98, SIN14[m] * INV98), acc);
        }
        float Cv, Sv; upk(acc, Cv, Sv);
        stcs(&yb[(h * 14 + w) * CC], Cv - Sv);
        if (w >= 1 && w <= 6)
            stcs(&yb[(h * 14 + 14 - w) * CC], Cv + Sv);
    }
}

__global__ __launch_bounds__(NTH, 5)
void gfilter_kernel(const float* __restrict__ x,
                    const float* __restrict__ wt,
                    float* __restrict__ y)
{
    DEF_TWIDDLES;
    // 56 pair-slots x 32 channels, 16B each; slot s = p*8 + kw holds
    // (F[p], F[14-p]) (p=0 -> (F[0], F[7])).
    extern __shared__ ulonglong2 sbuf[];

    const int tid  = threadIdx.x;
    const int cl   = tid & 31;
    const int role = tid >> 5;      // 0..7, one warp per role
    const int b    = blockIdx.y;
    const int c    = blockIdx.x * CB + cl;

    ulonglong2* bufc = sbuf + cl;   // index: slot*32
    const int base = (b * 196) * CC + c;
    const float* xg = x + base;

    const int hA = role;
    const int hB = (role == 0) ? 7 : 14 - role;

    // ---- Pass A: rfft over W for both rows of pair p, batched loads --------
    if (role < 7) {
        float xr0[14], xr1[14];
        #pragma unroll
        for (int w = 0; w < 14; ++w) xr0[w] = __ldg(&xg[(hA * 14 + w) * CC]);
        #pragma unroll
        for (int w = 0; w < 14; ++w) xr1[w] = __ldg(&xg[(hB * 14 + w) * CC]);
        ull eoA[7], eoB[7];
        #pragma unroll
        for (int j = 1; j <= 6; ++j) {
            eoA[j] = pk(xr0[j] + xr0[14 - j], xr0[j] - xr0[14 - j]);
            eoB[j] = pk(xr1[j] + xr1[14 - j], xr1[j] - xr1[14 - j]);
        }
        const float beA = xr0[0] + xr0[7], boA = xr0[0] - xr0[7];
        const float beB = xr1[0] + xr1[7], boB = xr1[0] - xr1[7];
        ull ePA[4], eMA[4], ePB[4], eMB[4];
        #pragma unroll
        for (int j = 1; j <= 3; ++j) {
            ePA[j] = f2fma(eoA[7 - j], pkc( 1.f, -1.f), eoA[j]);
            eMA[j] = f2fma(eoA[7 - j], pkc(-1.f,  1.f), eoA[j]);
            ePB[j] = f2fma(eoB[7 - j], pkc( 1.f, -1.f), eoB[j]);
            eMB[j] = f2fma(eoB[7 - j], pkc(-1.f,  1.f), eoB[j]);
        }
        #pragma unroll
        for (int kw = 0; kw < 8; ++kw) {
            ull aA = pk((kw & 1) ? boA : beA, 0.f);
            ull aB = pk((kw & 1) ? boB : beB, 0.f);
            #pragma unroll
            for (int j = 1; j <= 3; ++j) {
                const int m = (kw * j) % 14;
                aA = f2fma((kw & 1) ? eMA[j] : ePA[j],
                           pkc(COS14[m], -SIN14[m]), aA);
                aB = f2fma((kw & 1) ? eMB[j] : ePB[j],
                           pkc(COS14[m], -SIN14[m]), aB);
            }
            bufc[(role * 8 + kw) * 32] = make_ulonglong2(aA, aB);
        }
    }
    __syncthreads();

    // ---- Pass B: fwd H-DFT + weight + inv H-DFT, one kw column per warp ----
    {
        const int kw = role;
        const float2* wt2c = reinterpret_cast<const float2*>(wt) + c;

        ull E[7], OS[7];
        const ulonglong2 pr0 = bufc[(0 * 8 + kw) * 32];
        #pragma unroll
        for (int j = 1; j <= 6; ++j) {
            const ulonglong2 pr = bufc[(j * 8 + kw) * 32];
            E[j]  = f2add(pr.x, pr.y);
            OS[j] = swp(f2sub(pr.x, pr.y));
        }
        const ull fbp = f2add(pr0.x, pr0.y);
        const ull fbm = f2sub(pr0.x, pr0.y);
        ull EP[4], EM[4], OSM[4], OSP[4];
        #pragma unroll
        for (int j = 1; j <= 3; ++j) {
            EP[j]  = f2add(E[j],  E[7 - j]);
            EM[j]  = f2sub(E[j],  E[7 - j]);
            OSM[j] = f2sub(OS[j], OS[7 - j]);
            OSP[j] = f2add(OS[j], OS[7 - j]);
        }

        // kh = 0, 7 first (T = 0): gives inverse bases, X0/X7 die immediately
        ull ibp, ibm;
        {
            ull C, T;
            fwd_step<0>(EP, EM, OSM, OSP, fbp, fbm, C, T);
            const ull X0 = cmulw(C, wt2c[(0 * 8 + kw) * CC]);
            fwd_step<7>(EP, EM, OSM, OSP, fbp, fbm, C, T);
            const ull X7 = cmulw(C, wt2c[(7 * 8 + kw) * CC]);
            ibp = f2add(X0, X7);
            ibm = f2sub(X0, X7);
        }
        // pairs (J, 7-J): build inverse fold2 directly, EZ/OZS never stored
        ull EZP[4], EZM[4], OZM[4], OZP[4];
        #define PAIR_STEP(J)                                                   \
        {                                                                      \
            ull C, T;                                                          \
            fwd_step<J>(EP, EM, OSM, OSP, fbp, fbm, C, T);                     \
            ull Xa = cmulw(f2add(C, T), wt2c[((J) * 8 + kw) * CC]);            \
            ull Xb = cmulw(f2sub(C, T), wt2c[((14 - (J)) * 8 + kw) * CC]);     \
            const ull EZj  = f2add(Xa, Xb);                                    \
            const ull OZSj = swp(f2sub(Xa, Xb));                               \
            fwd_step<7 - (J)>(EP, EM, OSM, OSP, fbp, fbm, C, T);               \
            Xa = cmulw(f2add(C, T), wt2c[((7 - (J)) * 8 + kw) * CC]);          \
            Xb = cmulw(f2sub(C, T), wt2c[((7 + (J)) * 8 + kw) * CC]);          \
            const ull EZk  = f2add(Xa, Xb);                                    \
            const ull OZSk = swp(f2sub(Xa, Xb));                               \
            EZP[J] = f2add(EZj, EZk);  EZM[J] = f2sub(EZj, EZk);               \
            OZM[J] = f2sub(OZSj, OZSk); OZP[J] = f2add(OZSj, OZSk);            \
        }
        PAIR_STEP(1)
        PAIR_STEP(2)
        PAIR_STEP(3)
        #undef PAIR_STEP

        // inverse H-DFT, 3-term sums, store (Y_h, Y_{14-h}) pairs
        ull Y0sav = 0ull;
        #pragma unroll
        for (int h = 0; h < 8; ++h) {
            ull Cacc = (h & 1) ? ibm : ibp;
            ull Tacc = 0ull;
            #pragma unroll
            for (int j = 1; j <= 3; ++j) {
                const int m = (j * h) % 14;
                Cacc = f2fma((h & 1) ? EZM[j] : EZP[j], CP(COS14[m]), Cacc);
                if ((h % 7) != 0)
                    Tacc = f2fma((h & 1) ? OZP[j] : OZM[j],
                                 pkc(SIN14[m], -SIN14[m]), Tacc);
            }
            if (h == 0)       Y0sav = Cacc;
            else if (h == 7)  bufc[(0 * 8 + kw) * 32] =
                                  make_ulonglong2(Y0sav, Cacc);
            else
                bufc[(h * 8 + kw) * 32] =
                    make_ulonglong2(f2sub(Cacc, Tacc), f2add(Cacc, Tacc));
        }
    }
    __syncthreads();

    // ---- Pass C: c2r for both rows of pair p (pair loads) -------------------
    if (role < 7) {
        float* yb = y + base;
        ull yvA[8], yvB[8];
        #pragma unroll
        for (int kw = 0; kw < 8; ++kw) {
            const ulonglong2 v = bufc[(role * 8 + kw) * 32];
            yvA[kw] = v.x; yvB[kw] = v.y;
        }
        c2r_row(yb, hA, yvA);
        c2r_row(yb, hB, yvB);
    }
}

extern "C" void kernel_launch(void* const* d_in, const int* in_sizes, int n_in,
                              void* d_out, int out_size)
{
    (void)in_sizes; (void)n_in; (void)out_size;
    const float* x  = (const float*)d_in[0];
    const float* wt = (const float*)d_in[1];
    float* y        = (float*)d_out;

    const int smem_bytes = 56 * CB * (int)sizeof(ulonglong2); // 28672
    dim3 grid(CC / CB, 128); // (24, 128)
    gfilter_kernel<<<grid, NTH, smem_bytes>>>(x, wt, y);
}